// round 1
// baseline (speedup 1.0000x reference)
#include <cuda_runtime.h>
#include <math.h>
#include <stdint.h>

// ---------------- problem constants ----------------
#define BB   8192
#define KK   10
#define DD   128
#define TT   128
#define QDIM 256            // D + T
#define KDIM 384            // D + D + T
#define MU   (BB + BB*KK)   // 90112 rows in fused layer-1 pass
#define MKU  (MU*KK)        // 901120 neighbor pairs, layer-1
#define MKC  (BB*KK)        // 81920 neighbor pairs, layer-2

// ---------------- scratch (device globals; no allocations allowed) ----------------
__device__ float g_src  [(size_t)MU  * DD];    // emb0 of layer-1 "src" rows
__device__ float g_query[(size_t)MU  * QDIM];
__device__ float g_q    [(size_t)MU  * QDIM];
__device__ float g_keyv [(size_t)MKU * KDIM];
__device__ float g_k    [(size_t)MKU * QDIM];
__device__ float g_v    [(size_t)MKU * QDIM];
__device__ float g_ctx  [(size_t)MU  * QDIM];
__device__ float g_o    [(size_t)MU  * QDIM];
__device__ float g_gg   [(size_t)MU  * KDIM];
__device__ float g_h    [(size_t)MU  * DD];
__device__ float g_out1 [(size_t)MU  * DD];    // layer-1 outputs (src rows first, then hop-1 rows)
__device__ unsigned char g_inv[MU];

__device__ __forceinline__ float4 ldg4(const float* p) { return *(const float4*)p; }

// ---------------- GEMM: C[M,N] = A[M,Kd] * B[N,Kd]^T + bias, optional relu ----------------
// M % 128 == 0, N % 128 == 0, Kd % 16 == 0.  grid = (N/128, M/128), block = 256.
__global__ __launch_bounds__(256, 2)
void gemm_tn(const float* __restrict__ A, const float* __restrict__ Bw,
             const float* __restrict__ bias, float* __restrict__ C,
             int M, int N, int Kd, int relu)
{
    __shared__ float As[2][16][128];
    __shared__ float Bs[2][16][128];
    const int t  = threadIdx.x;
    const int m0 = blockIdx.y * 128;
    const int n0 = blockIdx.x * 128;
    const int tx = t & 15, ty = t >> 4;

    // each thread loads 2 float4 per tile (512 float4 = 128 rows x 16 k)
    const int ra0 = t >> 2;            // row 0..63
    const int ra1 = ra0 + 64;          // row 64..127
    const int ka0 = (t & 3) << 2;      // k offset 0,4,8,12

    const float* Ab = A  + (size_t)m0 * Kd;
    const float* Bb = Bw + (size_t)n0 * Kd;

    // preload tile 0
    {
        float4 a0 = ldg4(Ab + (size_t)ra0 * Kd + ka0);
        float4 a1 = ldg4(Ab + (size_t)ra1 * Kd + ka0);
        float4 b0 = ldg4(Bb + (size_t)ra0 * Kd + ka0);
        float4 b1 = ldg4(Bb + (size_t)ra1 * Kd + ka0);
        As[0][ka0+0][ra0] = a0.x; As[0][ka0+1][ra0] = a0.y; As[0][ka0+2][ra0] = a0.z; As[0][ka0+3][ra0] = a0.w;
        As[0][ka0+0][ra1] = a1.x; As[0][ka0+1][ra1] = a1.y; As[0][ka0+2][ra1] = a1.z; As[0][ka0+3][ra1] = a1.w;
        Bs[0][ka0+0][ra0] = b0.x; Bs[0][ka0+1][ra0] = b0.y; Bs[0][ka0+2][ra0] = b0.z; Bs[0][ka0+3][ra0] = b0.w;
        Bs[0][ka0+0][ra1] = b1.x; Bs[0][ka0+1][ra1] = b1.y; Bs[0][ka0+2][ra1] = b1.z; Bs[0][ka0+3][ra1] = b1.w;
    }
    __syncthreads();

    float acc[8][8];
    #pragma unroll
    for (int i = 0; i < 8; i++)
        #pragma unroll
        for (int j = 0; j < 8; j++) acc[i][j] = 0.f;

    const int nK = Kd >> 4;
    float4 pa0, pa1, pb0, pb1;
    for (int kt = 0; kt < nK; ++kt) {
        const int buf = kt & 1;
        if (kt + 1 < nK) {
            const int ko = (kt + 1) << 4;
            pa0 = ldg4(Ab + (size_t)ra0 * Kd + ko + ka0);
            pa1 = ldg4(Ab + (size_t)ra1 * Kd + ko + ka0);
            pb0 = ldg4(Bb + (size_t)ra0 * Kd + ko + ka0);
            pb1 = ldg4(Bb + (size_t)ra1 * Kd + ko + ka0);
        }
        #pragma unroll
        for (int kk = 0; kk < 16; ++kk) {
            float4 x0 = *(const float4*)&As[buf][kk][ty * 8];
            float4 x1 = *(const float4*)&As[buf][kk][ty * 8 + 4];
            float4 y0 = *(const float4*)&Bs[buf][kk][tx * 8];
            float4 y1 = *(const float4*)&Bs[buf][kk][tx * 8 + 4];
            float av[8] = {x0.x, x0.y, x0.z, x0.w, x1.x, x1.y, x1.z, x1.w};
            float bv8[8] = {y0.x, y0.y, y0.z, y0.w, y1.x, y1.y, y1.z, y1.w};
            #pragma unroll
            for (int i = 0; i < 8; i++)
                #pragma unroll
                for (int j = 0; j < 8; j++)
                    acc[i][j] += av[i] * bv8[j];
        }
        if (kt + 1 < nK) {
            const int nb = buf ^ 1;
            As[nb][ka0+0][ra0] = pa0.x; As[nb][ka0+1][ra0] = pa0.y; As[nb][ka0+2][ra0] = pa0.z; As[nb][ka0+3][ra0] = pa0.w;
            As[nb][ka0+0][ra1] = pa1.x; As[nb][ka0+1][ra1] = pa1.y; As[nb][ka0+2][ra1] = pa1.z; As[nb][ka0+3][ra1] = pa1.w;
            Bs[nb][ka0+0][ra0] = pb0.x; Bs[nb][ka0+1][ra0] = pb0.y; Bs[nb][ka0+2][ra0] = pb0.z; Bs[nb][ka0+3][ra0] = pb0.w;
            Bs[nb][ka0+0][ra1] = pb1.x; Bs[nb][ka0+1][ra1] = pb1.y; Bs[nb][ka0+2][ra1] = pb1.z; Bs[nb][ka0+3][ra1] = pb1.w;
            __syncthreads();
        }
    }

    #pragma unroll
    for (int i = 0; i < 8; i++) {
        const size_t crow = (size_t)(m0 + ty * 8 + i) * N + n0;
        #pragma unroll
        for (int j = 0; j < 8; j++) {
            float cv = acc[i][j] + bias[n0 + tx * 8 + j];
            if (relu) cv = fmaxf(cv, 0.f);
            C[crow + tx * 8 + j] = cv;
        }
    }
}

// ---------------- gather emb0 for layer-1 src rows (src_nodes ++ flattened neighbors1) ----------------
__global__ void gather_src_l1(const float* __restrict__ nf, const float* __restrict__ mem,
                              const int* __restrict__ src_nodes, const int* __restrict__ n1flat,
                              float* __restrict__ dst)
{
    const int m = blockIdx.x, t = threadIdx.x;             // 128 threads
    const int node = (m < BB) ? src_nodes[m] : n1flat[m - BB];
    dst[(size_t)m * DD + t] = nf[(size_t)node * DD + t] + mem[(size_t)node * DD + t];
}

// ---------------- query = [src_feat || cos(time_b)] ----------------
__global__ void build_query(const float* __restrict__ src, const float* __restrict__ time_b,
                            float* __restrict__ qry)
{
    const int m = blockIdx.x, t = threadIdx.x;             // 256 threads
    float v;
    if (t < DD) v = src[(size_t)m * DD + t];
    else        v = cosf(time_b[t - DD]);
    qry[(size_t)m * QDIM + t] = v;
}

// ---------------- keyv rows for fused layer-1 pass ----------------
__global__ void build_keyv_l1(const float* __restrict__ nf, const float* __restrict__ mem,
                              const float* __restrict__ ef,
                              const float* __restrict__ tw, const float* __restrict__ tb,
                              const int* __restrict__ n1, const int* __restrict__ e1,
                              const float* __restrict__ et1, const float* __restrict__ ts,
                              const int* __restrict__ n2, const int* __restrict__ e2,
                              const float* __restrict__ et2,
                              float* __restrict__ keyv)
{
    const int p = blockIdx.x, t = threadIdx.x;             // 128 threads, p = m*KK + j
    const int m = p / KK;
    int node, eidx; float tm, et;
    if (m < BB) {
        node = n1[p]; eidx = e1[p]; tm = ts[m]; et = et1[p];
    } else {
        const int mm = m - BB;
        const int pp = mm * KK + (p - m * KK);
        node = n2[pp]; eidx = e2[pp]; tm = ts[mm / KK]; et = et2[pp];
    }
    float* dst = keyv + (size_t)p * KDIM;
    dst[t]          = nf[(size_t)node * DD + t] + mem[(size_t)node * DD + t];
    dst[DD + t]     = ef[(size_t)eidx * DD + t];
    dst[2 * DD + t] = cosf((tm - et) * tw[t] + tb[t]);
}

// ---------------- keyv rows for layer-2 pass (neighbor emb = layer-1 outputs) ----------------
__global__ void build_keyv_l2(const float* __restrict__ nemb,   // g_out1 + BB*DD, [MKC, DD]
                              const float* __restrict__ ef,
                              const float* __restrict__ tw, const float* __restrict__ tb,
                              const int* __restrict__ e1, const float* __restrict__ et1,
                              const float* __restrict__ ts,
                              float* __restrict__ keyv)
{
    const int p = blockIdx.x, t = threadIdx.x;             // 128 threads
    const int m = p / KK;
    float* dst = keyv + (size_t)p * KDIM;
    dst[t]          = nemb[(size_t)p * DD + t];
    dst[DD + t]     = ef[(size_t)e1[p] * DD + t];
    dst[2 * DD + t] = cosf((ts[m] - et1[p]) * tw[t] + tb[t]);
}

// ---------------- scores + masked softmax + context ----------------
__global__ void attn_combine(const float* __restrict__ q, const float* __restrict__ k,
                             const float* __restrict__ v,
                             const int* __restrict__ neighA, const int* __restrict__ neighB,
                             int boundary,
                             float* __restrict__ ctx, unsigned char* __restrict__ inv)
{
    const int m = blockIdx.x, t = threadIdx.x;             // 256 threads
    __shared__ int   smask[KK];
    __shared__ float ssc[2][KK];
    __shared__ float sw[2][KK];

    if (t < KK) {
        const int* nb = (m < boundary) ? (neighA + (size_t)m * KK)
                                       : (neighB + (size_t)(m - boundary) * KK);
        smask[t] = (nb[t] == 0);
    }
    const int warp = t >> 5, lane = t & 31;
    for (int task = warp; task < 2 * KK; task += 8) {
        const int j = task >> 1, h = task & 1;
        const float* qr = q + (size_t)m * QDIM + h * 128;
        const float* kr = k + ((size_t)m * KK + j) * QDIM + h * 128;
        float s = 0.f;
        #pragma unroll
        for (int i = 0; i < 4; i++) { const int c = lane + 32 * i; s += qr[c] * kr[c]; }
        #pragma unroll
        for (int o = 16; o; o >>= 1) s += __shfl_xor_sync(0xffffffffu, s, o);
        if (lane == 0) ssc[h][j] = s * 0.08838834764831845f;   // 1/sqrt(128)
    }
    __syncthreads();

    if (t < 2) {
        const int h = t;
        int all1 = 1;
        #pragma unroll
        for (int j = 0; j < KK; j++) all1 &= smask[j];
        float sv[KK]; float mx = -3.0e38f;
        #pragma unroll
        for (int j = 0; j < KK; j++) {
            const int mk = smask[j] && !(all1 && j == 0);
            sv[j] = mk ? -1e9f : ssc[h][j];
            mx = fmaxf(mx, sv[j]);
        }
        float den = 0.f;
        #pragma unroll
        for (int j = 0; j < KK; j++) { const float e = expf(sv[j] - mx); sw[h][j] = e; den += e; }
        const float r = 1.f / den;
        #pragma unroll
        for (int j = 0; j < KK; j++) sw[h][j] *= r;
        if (t == 0) inv[m] = (unsigned char)all1;
    }
    __syncthreads();

    const int h = t >> 7;
    float acc = 0.f;
    #pragma unroll
    for (int j = 0; j < KK; j++)
        acc += sw[h][j] * v[((size_t)m * KK + j) * QDIM + t];
    ctx[(size_t)m * QDIM + t] = acc;
}

// ---------------- g = [invalid ? 0 : o  ||  src_feat] ----------------
__global__ void build_g(const float* __restrict__ o, const float* __restrict__ src,
                        const unsigned char* __restrict__ inv, float* __restrict__ gg)
{
    const int m = blockIdx.x, t = threadIdx.x;             // 384 threads
    float val;
    if (t < QDIM) val = inv[m] ? 0.f : o[(size_t)m * QDIM + t];
    else          val = src[(size_t)m * DD + (t - QDIM)];
    gg[(size_t)m * KDIM + t] = val;
}

// ---------------- host launcher ----------------
extern "C" void kernel_launch(void* const* d_in, const int* in_sizes, int n_in,
                              void* d_out, int out_size)
{
    const float* node_feat   = (const float*)d_in[0];
    const float* memory      = (const float*)d_in[1];
    const float* edge_feat   = (const float*)d_in[2];
    const float* time_w      = (const float*)d_in[3];
    const float* time_b      = (const float*)d_in[4];
    const float* Wq          = (const float*)d_in[5];
    const float* bq          = (const float*)d_in[6];
    const float* Wk          = (const float*)d_in[7];
    const float* bk          = (const float*)d_in[8];
    const float* Wv          = (const float*)d_in[9];
    const float* bv          = (const float*)d_in[10];
    const float* Wo          = (const float*)d_in[11];
    const float* bo          = (const float*)d_in[12];
    const float* W1          = (const float*)d_in[13];
    const float* b1          = (const float*)d_in[14];
    const float* W2          = (const float*)d_in[15];
    const float* b2          = (const float*)d_in[16];
    const float* timestamps  = (const float*)d_in[17];
    const int*   src_nodes   = (const int*)d_in[18];
    const int*   neighbors1  = (const int*)d_in[19];
    const int*   edge_idx1   = (const int*)d_in[20];
    const float* edge_times1 = (const float*)d_in[21];
    const int*   neighbors2  = (const int*)d_in[22];
    const int*   edge_idx2   = (const int*)d_in[23];
    const float* edge_times2 = (const float*)d_in[24];
    float* out = (float*)d_out;

    float *p_src, *p_query, *p_q, *p_keyv, *p_k, *p_v, *p_ctx, *p_o, *p_gg, *p_h, *p_out1;
    unsigned char* p_inv;
    cudaGetSymbolAddress((void**)&p_src,   g_src);
    cudaGetSymbolAddress((void**)&p_query, g_query);
    cudaGetSymbolAddress((void**)&p_q,     g_q);
    cudaGetSymbolAddress((void**)&p_keyv,  g_keyv);
    cudaGetSymbolAddress((void**)&p_k,     g_k);
    cudaGetSymbolAddress((void**)&p_v,     g_v);
    cudaGetSymbolAddress((void**)&p_ctx,   g_ctx);
    cudaGetSymbolAddress((void**)&p_o,     g_o);
    cudaGetSymbolAddress((void**)&p_gg,    g_gg);
    cudaGetSymbolAddress((void**)&p_h,     g_h);
    cudaGetSymbolAddress((void**)&p_out1,  g_out1);
    cudaGetSymbolAddress((void**)&p_inv,   g_inv);

    // ================= fused layer-1 pass (model 0), M = MU =================
    gather_src_l1<<<MU, DD>>>(node_feat, memory, src_nodes, neighbors1, p_src);
    build_query<<<MU, QDIM>>>(p_src, time_b, p_query);
    gemm_tn<<<dim3(QDIM/128, MU/128), 256>>>(p_query, Wq, bq, p_q, MU, QDIM, QDIM, 0);
    build_keyv_l1<<<MKU, DD>>>(node_feat, memory, edge_feat, time_w, time_b,
                               neighbors1, edge_idx1, edge_times1, timestamps,
                               neighbors2, edge_idx2, edge_times2, p_keyv);
    gemm_tn<<<dim3(QDIM/128, MKU/128), 256>>>(p_keyv, Wk, bk, p_k, MKU, QDIM, KDIM, 0);
    gemm_tn<<<dim3(QDIM/128, MKU/128), 256>>>(p_keyv, Wv, bv, p_v, MKU, QDIM, KDIM, 0);
    attn_combine<<<MU, 256>>>(p_q, p_k, p_v, neighbors1, neighbors2, BB, p_ctx, p_inv);
    gemm_tn<<<dim3(QDIM/128, MU/128), 256>>>(p_ctx, Wo, bo, p_o, MU, QDIM, QDIM, 0);
    build_g<<<MU, KDIM>>>(p_o, p_src, p_inv, p_gg);
    gemm_tn<<<dim3(DD/128, MU/128), 256>>>(p_gg, W1, b1, p_h, MU, DD, KDIM, 1);
    gemm_tn<<<dim3(DD/128, MU/128), 256>>>(p_h, W2, b2, p_out1, MU, DD, DD, 0);

    // ================= layer-2 pass (model 1), M = BB =================
    const float* Wq1 = Wq + QDIM * QDIM;  const float* bq1 = bq + QDIM;
    const float* Wk1 = Wk + QDIM * KDIM;  const float* bk1 = bk + QDIM;
    const float* Wv1 = Wv + QDIM * KDIM;  const float* bv1 = bv + QDIM;
    const float* Wo1 = Wo + QDIM * QDIM;  const float* bo1 = bo + QDIM;
    const float* W11 = W1 + DD * KDIM;    const float* b11 = b1 + DD;
    const float* W21 = W2 + DD * DD;      const float* b21 = b2 + DD;

    build_query<<<BB, QDIM>>>(p_out1, time_b, p_query);
    gemm_tn<<<dim3(QDIM/128, BB/128), 256>>>(p_query, Wq1, bq1, p_q, BB, QDIM, QDIM, 0);
    build_keyv_l2<<<MKC, DD>>>(p_out1 + (size_t)BB * DD, edge_feat, time_w, time_b,
                               edge_idx1, edge_times1, timestamps, p_keyv);
    gemm_tn<<<dim3(QDIM/128, MKC/128), 256>>>(p_keyv, Wk1, bk1, p_k, MKC, QDIM, KDIM, 0);
    gemm_tn<<<dim3(QDIM/128, MKC/128), 256>>>(p_keyv, Wv1, bv1, p_v, MKC, QDIM, KDIM, 0);
    attn_combine<<<BB, 256>>>(p_q, p_k, p_v, neighbors1, neighbors1, BB, p_ctx, p_inv);
    gemm_tn<<<dim3(QDIM/128, BB/128), 256>>>(p_ctx, Wo1, bo1, p_o, BB, QDIM, QDIM, 0);
    build_g<<<BB, KDIM>>>(p_o, p_out1, p_inv, p_gg);
    gemm_tn<<<dim3(DD/128, BB/128), 256>>>(p_gg, W11, b11, p_h, BB, DD, KDIM, 1);
    gemm_tn<<<dim3(DD/128, BB/128), 256>>>(p_h, W21, b21, out, BB, DD, DD, 0);
}

// round 5
// speedup vs baseline: 2.5521x; 2.5521x over previous
#include <cuda_runtime.h>
#include <cuda_bf16.h>
#include <math.h>
#include <stdint.h>

// ---------------- problem constants ----------------
#define BB   8192
#define KK   10
#define DD   128
#define TT   128
#define QDIM 256            // D + T
#define KDIM 384            // D + D + T
#define MU   (BB + BB*KK)   // 90112 rows in fused layer-1 pass
#define MKU  (MU*KK)        // 901120 neighbor pairs, layer-1
#define MKC  (BB*KK)        // 81920 neighbor pairs, layer-2

typedef __nv_bfloat16  bf16;
typedef __nv_bfloat162 bf162;

// ---------------- scratch (device globals; no allocations allowed) ----------------
__device__ __align__(16) bf16  g_src_h[(size_t)MU*DD],   g_src_l[(size_t)MU*DD];
__device__ __align__(16) float g_q   [(size_t)MU*QDIM];
__device__ __align__(16) bf16  g_kv_h[(size_t)MKU*KDIM], g_kv_l[(size_t)MKU*KDIM];
__device__ __align__(16) float g_k   [(size_t)MKU*QDIM];
__device__ __align__(16) float g_v   [(size_t)MKU*QDIM];
__device__ __align__(16) bf16  g_ctx_h[(size_t)MU*QDIM], g_ctx_l[(size_t)MU*QDIM];
__device__ __align__(16) float g_o   [(size_t)MU*QDIM];
__device__ __align__(16) bf16  g_gg_h[(size_t)MU*KDIM],  g_gg_l[(size_t)MU*KDIM];
__device__ __align__(16) bf16  g_h_h [(size_t)MU*DD],    g_h_l [(size_t)MU*DD];
__device__ __align__(16) bf16  g_o1_h[(size_t)MU*DD],    g_o1_l[(size_t)MU*DD];
__device__ __align__(16) float g_qb  [2*QDIM];
__device__ unsigned char g_inv[MU];
// weight planes (hi/lo bf16, packed to the K actually used by each GEMM)
__device__ __align__(16) bf16 w_q_h[2*QDIM*DD],   w_q_l[2*QDIM*DD];     // Wq cols 0..127 only
__device__ __align__(16) bf16 w_k_h[2*QDIM*KDIM], w_k_l[2*QDIM*KDIM];
__device__ __align__(16) bf16 w_v_h[2*QDIM*KDIM], w_v_l[2*QDIM*KDIM];
__device__ __align__(16) bf16 w_o_h[2*QDIM*QDIM], w_o_l[2*QDIM*QDIM];
__device__ __align__(16) bf16 w_1_h[2*DD*KDIM],   w_1_l[2*DD*KDIM];
__device__ __align__(16) bf16 w_2_h[2*DD*DD],     w_2_l[2*DD*DD];

// ---------------- helpers ----------------
__device__ __forceinline__ void cp_async16(uint32_t s, const void* g) {
    asm volatile("cp.async.cg.shared.global [%0], [%1], 16;" :: "r"(s), "l"(g));
}
__device__ __forceinline__ void mma16(float* c, const uint32_t* a, const uint32_t* b) {
    asm volatile("mma.sync.aligned.m16n8k16.row.col.f32.bf16.bf16.f32 "
        "{%0,%1,%2,%3},{%4,%5,%6,%7},{%8,%9},{%0,%1,%2,%3};"
        : "+f"(c[0]), "+f"(c[1]), "+f"(c[2]), "+f"(c[3])
        : "r"(a[0]), "r"(a[1]), "r"(a[2]), "r"(a[3]), "r"(b[0]), "r"(b[1]));
}
__device__ __forceinline__ void split1(float x, bf16* hp, bf16* lp) {
    bf16 h = __float2bfloat16(x);
    *hp = h; *lp = __float2bfloat16(x - __bfloat162float(h));
}
__device__ __forceinline__ void split4(bf16* hp, bf16* lp, float4 v) {
    bf16 hx = __float2bfloat16(v.x), hy = __float2bfloat16(v.y);
    bf16 hz = __float2bfloat16(v.z), hw = __float2bfloat16(v.w);
    ((bf162*)hp)[0] = __halves2bfloat162(hx, hy);
    ((bf162*)hp)[1] = __halves2bfloat162(hz, hw);
    ((bf162*)lp)[0] = __halves2bfloat162(__float2bfloat16(v.x - __bfloat162float(hx)),
                                         __float2bfloat16(v.y - __bfloat162float(hy)));
    ((bf162*)lp)[1] = __halves2bfloat162(__float2bfloat16(v.z - __bfloat162float(hz)),
                                         __float2bfloat16(v.w - __bfloat162float(hw)));
}

// ---------------- split-bf16 tensor-core GEMM ----------------
// C[M,Nper] = A[M,Kd] * B[Nper,Kd]^T + bias (A,B given as hi/lo bf16 planes).
// 3 MMAs per step: hi*hi + lo*hi + hi*lo. Dual weight sets via grid.x.
#define BK    32
#define BKP   40                 // padded smem row (bf16 elems)
#define STG_E (128*BKP)          // elems per plane per stage

extern __shared__ bf16 sm_dyn[];

__global__ __launch_bounds__(256, 2)
void gemm_bf16s(const bf16* __restrict__ Ah, const bf16* __restrict__ Al,
                const bf16* __restrict__ B0h, const bf16* __restrict__ B0l, const float* __restrict__ bias0,
                const bf16* __restrict__ B1h, const bf16* __restrict__ B1l, const float* __restrict__ bias1,
                int Nper, int Kd, int relu, int split,
                float* __restrict__ C0f, float* __restrict__ C1f,
                bf16* __restrict__ C0h, bf16* __restrict__ C0l,
                bf16* __restrict__ C1h, bf16* __restrict__ C1l)
{
    const int t  = threadIdx.x;
    const int m0 = blockIdx.y * 128;
    const int nblk = Nper / 128;
    const bf16 *Bh, *Bl; const float* bias; float* Cf; bf16 *Ch, *Cl; int n0;
    if ((int)blockIdx.x < nblk) { Bh=B0h; Bl=B0l; bias=bias0; Cf=C0f; Ch=C0h; Cl=C0l; n0=blockIdx.x*128; }
    else                        { Bh=B1h; Bl=B1l; bias=bias1; Cf=C1f; Ch=C1h; Cl=C1l; n0=(blockIdx.x-nblk)*128; }

    bf16* sAh = sm_dyn;                // each plane: [2 stages][STG_E]
    bf16* sAl = sm_dyn + 2*STG_E;
    bf16* sBh = sm_dyn + 4*STG_E;
    bf16* sBl = sm_dyn + 6*STG_E;

    const int warp = t >> 5, lane = t & 31;
    const int wm = (warp & 3) * 32, wn = (warp >> 2) * 64;
    const int g = lane >> 2, tig = lane & 3;

    const bf16* Abh = Ah + (size_t)m0 * Kd;
    const bf16* Abl = Al + (size_t)m0 * Kd;
    const bf16* Bbh = Bh + (size_t)n0 * Kd;
    const bf16* Bbl = Bl + (size_t)n0 * Kd;

    const uint32_t s0 = (uint32_t)__cvta_generic_to_shared(sm_dyn);
    const int nK = Kd / BK;

    auto issue = [&](int kt, int buf) {
        const int ko = kt * BK;
        const uint32_t stg = s0 + (uint32_t)buf * (STG_E * 2);
        #pragma unroll
        for (int c = t; c < 512; c += 256) {
            const int r = c >> 2, off = (c & 3) * 8;
            const uint32_t da = (uint32_t)((r * BKP + off) * 2);
            const size_t gof = (size_t)r * Kd + ko + off;
            cp_async16(stg + da,               Abh + gof);
            cp_async16(stg + 4*STG_E + da,     Abl + gof);
        }
        #pragma unroll
        for (int c = t; c < 512; c += 256) {
            const int r = c >> 2, off = (c & 3) * 8;
            const uint32_t da = (uint32_t)((r * BKP + off) * 2);
            const size_t gof = (size_t)r * Kd + ko + off;
            cp_async16(stg + 8*STG_E + da,     Bbh + gof);
            cp_async16(stg + 12*STG_E + da,    Bbl + gof);
        }
        asm volatile("cp.async.commit_group;" ::: "memory");
    };

    float acc[2][8][4];
    #pragma unroll
    for (int mi = 0; mi < 2; mi++)
        #pragma unroll
        for (int ni = 0; ni < 8; ni++)
            #pragma unroll
            for (int x = 0; x < 4; x++) acc[mi][ni][x] = 0.f;

    issue(0, 0);
    for (int kt = 0; kt < nK; kt++) {
        const int buf = kt & 1;
        if (kt + 1 < nK) { issue(kt + 1, buf ^ 1); asm volatile("cp.async.wait_group 1;" ::: "memory"); }
        else             { asm volatile("cp.async.wait_group 0;" ::: "memory"); }
        __syncthreads();
        const bf16* Ahb = sAh + buf * STG_E;
        const bf16* Alb = sAl + buf * STG_E;
        const bf16* Bhb = sBh + buf * STG_E;
        const bf16* Blb = sBl + buf * STG_E;
        #pragma unroll
        for (int kk = 0; kk < BK; kk += 16) {
            uint32_t ah[2][4], ax[2][4], bx[8][2];
            #pragma unroll
            for (int mi = 0; mi < 2; mi++) {
                const bf16* p = Ahb + (wm + mi*16 + g) * BKP + kk + tig*2;
                ah[mi][0] = *(const uint32_t*)p;
                ah[mi][1] = *(const uint32_t*)(p + 8*BKP);
                ah[mi][2] = *(const uint32_t*)(p + 8);
                ah[mi][3] = *(const uint32_t*)(p + 8*BKP + 8);
            }
            #pragma unroll
            for (int ni = 0; ni < 8; ni++) {
                const bf16* p = Bhb + (wn + ni*8 + g) * BKP + kk + tig*2;
                bx[ni][0] = *(const uint32_t*)p;
                bx[ni][1] = *(const uint32_t*)(p + 8);
            }
            #pragma unroll
            for (int mi = 0; mi < 2; mi++)
                #pragma unroll
                for (int ni = 0; ni < 8; ni++) mma16(acc[mi][ni], ah[mi], bx[ni]);   // hi*hi
            #pragma unroll
            for (int mi = 0; mi < 2; mi++) {
                const bf16* p = Alb + (wm + mi*16 + g) * BKP + kk + tig*2;
                ax[mi][0] = *(const uint32_t*)p;
                ax[mi][1] = *(const uint32_t*)(p + 8*BKP);
                ax[mi][2] = *(const uint32_t*)(p + 8);
                ax[mi][3] = *(const uint32_t*)(p + 8*BKP + 8);
            }
            #pragma unroll
            for (int mi = 0; mi < 2; mi++)
                #pragma unroll
                for (int ni = 0; ni < 8; ni++) mma16(acc[mi][ni], ax[mi], bx[ni]);   // lo*hi
            #pragma unroll
            for (int ni = 0; ni < 8; ni++) {
                const bf16* p = Blb + (wn + ni*8 + g) * BKP + kk + tig*2;
                bx[ni][0] = *(const uint32_t*)p;
                bx[ni][1] = *(const uint32_t*)(p + 8);
            }
            #pragma unroll
            for (int mi = 0; mi < 2; mi++)
                #pragma unroll
                for (int ni = 0; ni < 8; ni++) mma16(acc[mi][ni], ah[mi], bx[ni]);   // hi*lo
        }
        __syncthreads();
    }

    #pragma unroll
    for (int mi = 0; mi < 2; mi++) {
        const int row0 = m0 + wm + mi*16 + g;
        #pragma unroll
        for (int ni = 0; ni < 8; ni++) {
            const int col = n0 + wn + ni*8 + 2*tig;
            const float b0v = bias[col], b1v = bias[col + 1];
            float v0 = acc[mi][ni][0] + b0v, v1 = acc[mi][ni][1] + b1v;
            float v2 = acc[mi][ni][2] + b0v, v3 = acc[mi][ni][3] + b1v;
            if (relu) { v0 = fmaxf(v0,0.f); v1 = fmaxf(v1,0.f); v2 = fmaxf(v2,0.f); v3 = fmaxf(v3,0.f); }
            if (!split) {
                *(float2*)(Cf + (size_t)row0 * Nper + col)     = make_float2(v0, v1);
                *(float2*)(Cf + (size_t)(row0+8) * Nper + col) = make_float2(v2, v3);
            } else {
                bf16 h0 = __float2bfloat16(v0), h1 = __float2bfloat16(v1);
                bf16 h2 = __float2bfloat16(v2), h3 = __float2bfloat16(v3);
                *(bf162*)(Ch + (size_t)row0 * Nper + col)     = __halves2bfloat162(h0, h1);
                *(bf162*)(Ch + (size_t)(row0+8) * Nper + col) = __halves2bfloat162(h2, h3);
                *(bf162*)(Cl + (size_t)row0 * Nper + col)     =
                    __halves2bfloat162(__float2bfloat16(v0 - __bfloat162float(h0)),
                                       __float2bfloat16(v1 - __bfloat162float(h1)));
                *(bf162*)(Cl + (size_t)(row0+8) * Nper + col) =
                    __halves2bfloat162(__float2bfloat16(v2 - __bfloat162float(h2)),
                                       __float2bfloat16(v3 - __bfloat162float(h3)));
            }
        }
    }
}

// ---------------- weight splitter: packed [rows, cols] hi/lo from fp32 [rows, ld] ----------------
__global__ void split_w(const float* __restrict__ src, bf16* __restrict__ hi, bf16* __restrict__ lo,
                        int total, int cols, int ld)
{
    const int i = blockIdx.x * 256 + threadIdx.x;
    if (i >= total) return;
    const int r = i / cols, c = i - r * cols;
    split1(src[(size_t)r * ld + c], hi + i, lo + i);
}

// ---------------- effective Q bias: qb[model][n] = bq[n] + sum_t Wq[n][128+t]*cos(tb[t]) ----------------
__global__ void make_qbias(const float* __restrict__ Wq, const float* __restrict__ bq,
                           const float* __restrict__ tb, float* __restrict__ qb)
{
    const int model = blockIdx.x, n = threadIdx.x;     // grid 2, block 256
    const float* w = Wq + (size_t)model * QDIM * QDIM + (size_t)n * QDIM + DD;
    float s = bq[model * QDIM + n];
    for (int t = 0; t < TT; t++) s += w[t] * cosf(tb[t]);
    qb[model * QDIM + n] = s;
}

// ---------------- gather emb0 for layer-1 src rows ----------------
__global__ void gather_src_l1(const float* __restrict__ nf, const float* __restrict__ mem,
                              const int* __restrict__ src_nodes, const int* __restrict__ n1flat,
                              bf16* __restrict__ dh, bf16* __restrict__ dl)
{
    const int m = blockIdx.x * 4 + (threadIdx.x >> 5);
    const int lane = threadIdx.x & 31;
    const int node = (m < BB) ? src_nodes[m] : n1flat[m - BB];
    const float4 a = ((const float4*)(nf  + (size_t)node * DD))[lane];
    const float4 b = ((const float4*)(mem + (size_t)node * DD))[lane];
    split4(dh + (size_t)m*DD + lane*4, dl + (size_t)m*DD + lane*4,
           make_float4(a.x+b.x, a.y+b.y, a.z+b.z, a.w+b.w));
}

// ---------------- keyv rows, layer-1 fused pass ----------------
__global__ void build_keyv_l1(const float* __restrict__ nf, const float* __restrict__ mem,
                              const float* __restrict__ ef,
                              const float* __restrict__ tw, const float* __restrict__ tb,
                              const int* __restrict__ n1, const int* __restrict__ e1,
                              const float* __restrict__ et1, const float* __restrict__ ts,
                              const int* __restrict__ n2, const int* __restrict__ e2,
                              const float* __restrict__ et2,
                              bf16* __restrict__ kvh, bf16* __restrict__ kvl)
{
    const int p = blockIdx.x * 4 + (threadIdx.x >> 5);
    const int lane = threadIdx.x & 31;
    const int m = p / KK;
    int node, eidx; float tm, et;
    if (m < BB) { node = n1[p]; eidx = e1[p]; tm = ts[m]; et = et1[p]; }
    else {
        const int pp = p - BB * KK;
        node = n2[pp]; eidx = e2[pp]; tm = ts[(m - BB) / KK]; et = et2[pp];
    }
    const float4 a = ((const float4*)(nf  + (size_t)node * DD))[lane];
    const float4 b = ((const float4*)(mem + (size_t)node * DD))[lane];
    const float4 e = ((const float4*)(ef  + (size_t)eidx * DD))[lane];
    const float4 w = ((const float4*)tw)[lane];
    const float4 bb = ((const float4*)tb)[lane];
    const float dt = tm - et;
    const size_t base = (size_t)p * KDIM + lane*4;
    split4(kvh + base,        kvl + base,        make_float4(a.x+b.x, a.y+b.y, a.z+b.z, a.w+b.w));
    split4(kvh + base + DD,   kvl + base + DD,   e);
    split4(kvh + base + 2*DD, kvl + base + 2*DD,
           make_float4(cosf(dt*w.x+bb.x), cosf(dt*w.y+bb.y), cosf(dt*w.z+bb.z), cosf(dt*w.w+bb.w)));
}

// ---------------- keyv rows, layer-2 pass (neighbor emb copied from out1 planes) ----------------
__global__ void build_keyv_l2(const bf16* __restrict__ nh, const bf16* __restrict__ nl,  // [MKC, DD]
                              const float* __restrict__ ef,
                              const float* __restrict__ tw, const float* __restrict__ tb,
                              const int* __restrict__ e1, const float* __restrict__ et1,
                              const float* __restrict__ ts,
                              bf16* __restrict__ kvh, bf16* __restrict__ kvl)
{
    const int p = blockIdx.x * 4 + (threadIdx.x >> 5);
    const int lane = threadIdx.x & 31;
    const int m = p / KK;
    const float4 e  = ((const float4*)(ef + (size_t)e1[p] * DD))[lane];
    const float4 w  = ((const float4*)tw)[lane];
    const float4 bb = ((const float4*)tb)[lane];
    const float dt = ts[m] - et1[p];
    const size_t base = (size_t)p * KDIM + lane*4;
    ((uint2*)(kvh + (size_t)p*KDIM))[lane] = ((const uint2*)(nh + (size_t)p*DD))[lane];
    ((uint2*)(kvl + (size_t)p*KDIM))[lane] = ((const uint2*)(nl + (size_t)p*DD))[lane];
    split4(kvh + base + DD,   kvl + base + DD,   e);
    split4(kvh + base + 2*DD, kvl + base + 2*DD,
           make_float4(cosf(dt*w.x+bb.x), cosf(dt*w.y+bb.y), cosf(dt*w.z+bb.z), cosf(dt*w.w+bb.w)));
}

// ---------------- scores + masked softmax + context ----------------
__global__ void attn_combine(const float* __restrict__ q, const float* __restrict__ k,
                             const float* __restrict__ v,
                             const int* __restrict__ neighA, const int* __restrict__ neighB,
                             int boundary,
                             bf16* __restrict__ ch, bf16* __restrict__ cl,
                             unsigned char* __restrict__ inv)
{
    const int m = blockIdx.x, t = threadIdx.x;             // 256 threads
    __shared__ int   smask[KK];
    __shared__ float ssc[2][KK];
    __shared__ float sw[2][KK];

    if (t < KK) {
        const int* nb = (m < boundary) ? (neighA + (size_t)m * KK)
                                       : (neighB + (size_t)(m - boundary) * KK);
        smask[t] = (nb[t] == 0);
    }
    const int warp = t >> 5, lane = t & 31;
    for (int task = warp; task < 2 * KK; task += 8) {
        const int j = task >> 1, h = task & 1;
        const float* qr = q + (size_t)m * QDIM + h * 128;
        const float* kr = k + ((size_t)m * KK + j) * QDIM + h * 128;
        float s = 0.f;
        #pragma unroll
        for (int i = 0; i < 4; i++) { const int c = lane + 32 * i; s += qr[c] * kr[c]; }
        #pragma unroll
        for (int o = 16; o; o >>= 1) s += __shfl_xor_sync(0xffffffffu, s, o);
        if (lane == 0) ssc[h][j] = s * 0.08838834764831845f;   // 1/sqrt(128)
    }
    __syncthreads();

    if (t < 2) {
        const int h = t;
        int all1 = 1;
        #pragma unroll
        for (int j = 0; j < KK; j++) all1 &= smask[j];
        float sv[KK]; float mx = -3.0e38f;
        #pragma unroll
        for (int j = 0; j < KK; j++) {
            const int mk = smask[j] && !(all1 && j == 0);
            sv[j] = mk ? -1e9f : ssc[h][j];
            mx = fmaxf(mx, sv[j]);
        }
        float den = 0.f;
        #pragma unroll
        for (int j = 0; j < KK; j++) { const float e = expf(sv[j] - mx); sw[h][j] = e; den += e; }
        const float r = 1.f / den;
        #pragma unroll
        for (int j = 0; j < KK; j++) sw[h][j] *= r;
        if (t == 0) inv[m] = (unsigned char)all1;
    }
    __syncthreads();

    const int h = t >> 7;
    float acc = 0.f;
    #pragma unroll
    for (int j = 0; j < KK; j++)
        acc += sw[h][j] * v[((size_t)m * KK + j) * QDIM + t];
    split1(acc, ch + (size_t)m * QDIM + t, cl + (size_t)m * QDIM + t);
}

// ---------------- g = [invalid ? 0 : o  ||  src_feat] ----------------
__global__ void build_g(const float* __restrict__ o,
                        const bf16* __restrict__ sh, const bf16* __restrict__ sl,
                        const unsigned char* __restrict__ inv,
                        bf16* __restrict__ gh, bf16* __restrict__ gl)
{
    const int m = blockIdx.x, t = threadIdx.x;             // 384 threads
    const size_t idx = (size_t)m * KDIM + t;
    if (t < QDIM) {
        const float val = inv[m] ? 0.f : o[(size_t)m * QDIM + t];
        split1(val, gh + idx, gl + idx);
    } else {
        gh[idx] = sh[(size_t)m * DD + (t - QDIM)];
        gl[idx] = sl[(size_t)m * DD + (t - QDIM)];
    }
}

// ---------------- host launcher ----------------
#define GEMM_SMEM (8 * STG_E * 2)    // 81920 bytes

extern "C" void kernel_launch(void* const* d_in, const int* in_sizes, int n_in,
                              void* d_out, int out_size)
{
    const float* node_feat   = (const float*)d_in[0];
    const float* memory      = (const float*)d_in[1];
    const float* edge_feat   = (const float*)d_in[2];
    const float* time_w      = (const float*)d_in[3];
    const float* time_b      = (const float*)d_in[4];
    const float* Wq          = (const float*)d_in[5];
    const float* bq          = (const float*)d_in[6];
    const float* Wk          = (const float*)d_in[7];
    const float* bk          = (const float*)d_in[8];
    const float* Wv          = (const float*)d_in[9];
    const float* bv          = (const float*)d_in[10];
    const float* Wo          = (const float*)d_in[11];
    const float* bo          = (const float*)d_in[12];
    const float* W1          = (const float*)d_in[13];
    const float* b1          = (const float*)d_in[14];
    const float* W2          = (const float*)d_in[15];
    const float* b2          = (const float*)d_in[16];
    const float* timestamps  = (const float*)d_in[17];
    const int*   src_nodes   = (const int*)d_in[18];
    const int*   neighbors1  = (const int*)d_in[19];
    const int*   edge_idx1   = (const int*)d_in[20];
    const float* edge_times1 = (const float*)d_in[21];
    const int*   neighbors2  = (const int*)d_in[22];
    const int*   edge_idx2   = (const int*)d_in[23];
    const float* edge_times2 = (const float*)d_in[24];
    float* out = (float*)d_out;

    bf16 *srch, *srcl, *kvh, *kvl, *ctxh, *ctxl, *ggh, *ggl, *hh, *hl, *o1h, *o1l;
    bf16 *wqh, *wql, *wkh, *wkl, *wvh, *wvl, *woh, *wol, *w1h, *w1l, *w2h, *w2l;
    float *pq, *pk, *pv, *po, *pqb;
    unsigned char* pinv;
    cudaGetSymbolAddress((void**)&srch, g_src_h); cudaGetSymbolAddress((void**)&srcl, g_src_l);
    cudaGetSymbolAddress((void**)&kvh,  g_kv_h);  cudaGetSymbolAddress((void**)&kvl,  g_kv_l);
    cudaGetSymbolAddress((void**)&ctxh, g_ctx_h); cudaGetSymbolAddress((void**)&ctxl, g_ctx_l);
    cudaGetSymbolAddress((void**)&ggh,  g_gg_h);  cudaGetSymbolAddress((void**)&ggl,  g_gg_l);
    cudaGetSymbolAddress((void**)&hh,   g_h_h);   cudaGetSymbolAddress((void**)&hl,   g_h_l);
    cudaGetSymbolAddress((void**)&o1h,  g_o1_h);  cudaGetSymbolAddress((void**)&o1l,  g_o1_l);
    cudaGetSymbolAddress((void**)&wqh,  w_q_h);   cudaGetSymbolAddress((void**)&wql,  w_q_l);
    cudaGetSymbolAddress((void**)&wkh,  w_k_h);   cudaGetSymbolAddress((void**)&wkl,  w_k_l);
    cudaGetSymbolAddress((void**)&wvh,  w_v_h);   cudaGetSymbolAddress((void**)&wvl,  w_v_l);
    cudaGetSymbolAddress((void**)&woh,  w_o_h);   cudaGetSymbolAddress((void**)&wol,  w_o_l);
    cudaGetSymbolAddress((void**)&w1h,  w_1_h);   cudaGetSymbolAddress((void**)&w1l,  w_1_l);
    cudaGetSymbolAddress((void**)&w2h,  w_2_h);   cudaGetSymbolAddress((void**)&w2l,  w_2_l);
    cudaGetSymbolAddress((void**)&pq,   g_q);     cudaGetSymbolAddress((void**)&pk,   g_k);
    cudaGetSymbolAddress((void**)&pv,   g_v);     cudaGetSymbolAddress((void**)&po,   g_o);
    cudaGetSymbolAddress((void**)&pqb,  g_qb);    cudaGetSymbolAddress((void**)&pinv, g_inv);

    cudaFuncSetAttribute(gemm_bf16s, cudaFuncAttributeMaxDynamicSharedMemorySize, GEMM_SMEM);

    // ---- weight prep (tiny) ----
    make_qbias<<<2, QDIM>>>(Wq, bq, time_b, pqb);
    split_w<<<(2*QDIM*DD   + 255)/256, 256>>>(Wq, wqh, wql, 2*QDIM*DD,   DD,   QDIM);
    split_w<<<(2*QDIM*KDIM + 255)/256, 256>>>(Wk, wkh, wkl, 2*QDIM*KDIM, KDIM, KDIM);
    split_w<<<(2*QDIM*KDIM + 255)/256, 256>>>(Wv, wvh, wvl, 2*QDIM*KDIM, KDIM, KDIM);
    split_w<<<(2*QDIM*QDIM + 255)/256, 256>>>(Wo, woh, wol, 2*QDIM*QDIM, QDIM, QDIM);
    split_w<<<(2*DD*KDIM   + 255)/256, 256>>>(W1, w1h, w1l, 2*DD*KDIM,   KDIM, KDIM);
    split_w<<<(2*DD*DD     + 255)/256, 256>>>(W2, w2h, w2l, 2*DD*DD,     DD,   DD);

    // model-1 plane offsets
    const int OQ = QDIM*DD, OK = QDIM*KDIM, OO = QDIM*QDIM, O1 = DD*KDIM, O2 = DD*DD;
    const float* bk1 = bk + QDIM; const float* bv1 = bv + QDIM; const float* bo1 = bo + QDIM;
    const float* b11 = b1 + DD;   const float* b21 = b2 + DD;

    // ================= fused layer-1 pass (model 0), M = MU =================
    gather_src_l1<<<MU/4, 128>>>(node_feat, memory, src_nodes, neighbors1, srch, srcl);
    gemm_bf16s<<<dim3(2, MU/128), 256, GEMM_SMEM>>>(srch, srcl, wqh, wql, pqb, wqh, wql, pqb,
        QDIM, DD, 0, 0, pq, pq, 0, 0, 0, 0);
    build_keyv_l1<<<MKU/4, 128>>>(node_feat, memory, edge_feat, time_w, time_b,
                                  neighbors1, edge_idx1, edge_times1, timestamps,
                                  neighbors2, edge_idx2, edge_times2, kvh, kvl);
    gemm_bf16s<<<dim3(4, MKU/128), 256, GEMM_SMEM>>>(kvh, kvl, wkh, wkl, bk, wvh, wvl, bv,
        QDIM, KDIM, 0, 0, pk, pv, 0, 0, 0, 0);
    attn_combine<<<MU, 256>>>(pq, pk, pv, neighbors1, neighbors2, BB, ctxh, ctxl, pinv);
    gemm_bf16s<<<dim3(2, MU/128), 256, GEMM_SMEM>>>(ctxh, ctxl, woh, wol, bo, woh, wol, bo,
        QDIM, QDIM, 0, 0, po, po, 0, 0, 0, 0);
    build_g<<<MU, KDIM>>>(po, srch, srcl, pinv, ggh, ggl);
    gemm_bf16s<<<dim3(1, MU/128), 256, GEMM_SMEM>>>(ggh, ggl, w1h, w1l, b1, w1h, w1l, b1,
        DD, KDIM, 1, 1, 0, 0, hh, hl, hh, hl);
    gemm_bf16s<<<dim3(1, MU/128), 256, GEMM_SMEM>>>(hh, hl, w2h, w2l, b2, w2h, w2l, b2,
        DD, DD, 0, 1, 0, 0, o1h, o1l, o1h, o1l);

    // ================= layer-2 pass (model 1), M = BB =================
    gemm_bf16s<<<dim3(2, BB/128), 256, GEMM_SMEM>>>(o1h, o1l, wqh+OQ, wql+OQ, pqb+QDIM, wqh+OQ, wql+OQ, pqb+QDIM,
        QDIM, DD, 0, 0, pq, pq, 0, 0, 0, 0);
    build_keyv_l2<<<MKC/4, 128>>>(o1h + (size_t)BB*DD, o1l + (size_t)BB*DD, edge_feat, time_w, time_b,
                                  edge_idx1, edge_times1, timestamps, kvh, kvl);
    gemm_bf16s<<<dim3(4, MKC/128), 256, GEMM_SMEM>>>(kvh, kvl, wkh+OK, wkl+OK, bk1, wvh+OK, wvl+OK, bv1,
        QDIM, KDIM, 0, 0, pk, pv, 0, 0, 0, 0);
    attn_combine<<<BB, 256>>>(pq, pk, pv, neighbors1, neighbors1, BB, ctxh, ctxl, pinv);
    gemm_bf16s<<<dim3(2, BB/128), 256, GEMM_SMEM>>>(ctxh, ctxl, woh+OO, wol+OO, bo1, woh+OO, wol+OO, bo1,
        QDIM, QDIM, 0, 0, po, po, 0, 0, 0, 0);
    build_g<<<BB, KDIM>>>(po, o1h, o1l, pinv, ggh, ggl);
    gemm_bf16s<<<dim3(1, BB/128), 256, GEMM_SMEM>>>(ggh, ggl, w1h+O1, w1l+O1, b11, w1h+O1, w1l+O1, b11,
        DD, KDIM, 1, 1, 0, 0, hh, hl, hh, hl);
    gemm_bf16s<<<dim3(1, BB/128), 256, GEMM_SMEM>>>(hh, hl, w2h+O2, w2l+O2, b21, w2h+O2, w2l+O2, b21,
        DD, DD, 0, 0, out, out, 0, 0, 0, 0);
}

// round 8
// speedup vs baseline: 2.6019x; 1.0195x over previous
#include <cuda_runtime.h>
#include <cuda_bf16.h>
#include <math.h>
#include <stdint.h>

// ---------------- problem constants ----------------
#define BB   8192
#define KK   10
#define DD   128
#define TT   128
#define QDIM 256            // D + T
#define KDIM 384            // D + D + T
#define MU   (BB + BB*KK)   // 90112 rows in fused layer-1 pass
#define MKU  (MU*KK)        // 901120 neighbor pairs, layer-1
#define MKC  (BB*KK)        // 81920 neighbor pairs, layer-2

typedef __nv_bfloat16  bf16;
typedef __nv_bfloat162 bf162;

// ---------------- scratch (device globals; no allocations allowed) ----------------
__device__ __align__(16) bf16  g_src_h[(size_t)MU*DD],   g_src_l[(size_t)MU*DD];
__device__ __align__(16) float g_q   [(size_t)MU*QDIM];
__device__ __align__(16) bf16  g_kv_h[(size_t)MKU*KDIM], g_kv_l[(size_t)MKU*KDIM];
__device__ __align__(16) float g_k   [(size_t)MKU*QDIM];
__device__ __align__(16) float g_v   [(size_t)MKU*QDIM];
__device__ __align__(16) bf16  g_ctx_h[(size_t)MU*QDIM], g_ctx_l[(size_t)MU*QDIM];
__device__ __align__(16) float g_o   [(size_t)MU*QDIM];
__device__ __align__(16) bf16  g_gg_h[(size_t)MU*KDIM],  g_gg_l[(size_t)MU*KDIM];
__device__ __align__(16) bf16  g_h_h [(size_t)MU*DD],    g_h_l [(size_t)MU*DD];
__device__ __align__(16) bf16  g_o1_h[(size_t)MU*DD],    g_o1_l[(size_t)MU*DD];
__device__ __align__(16) float g_qb  [2*QDIM];
__device__ unsigned char g_inv[MU];
// weight planes (hi/lo bf16, packed to the K actually used by each GEMM)
__device__ __align__(16) bf16 w_q_h[2*QDIM*DD],   w_q_l[2*QDIM*DD];     // Wq cols 0..127 only
__device__ __align__(16) bf16 w_k_h[2*QDIM*KDIM], w_k_l[2*QDIM*KDIM];
__device__ __align__(16) bf16 w_v_h[2*QDIM*KDIM], w_v_l[2*QDIM*KDIM];
__device__ __align__(16) bf16 w_o_h[2*QDIM*QDIM], w_o_l[2*QDIM*QDIM];
__device__ __align__(16) bf16 w_1_h[2*DD*KDIM],   w_1_l[2*DD*KDIM];
__device__ __align__(16) bf16 w_2_h[2*DD*DD],     w_2_l[2*DD*DD];

// ---------------- helpers ----------------
__device__ __forceinline__ void cp_async16(uint32_t s, const void* g) {
    asm volatile("cp.async.cg.shared.global [%0], [%1], 16;" :: "r"(s), "l"(g));
}
__device__ __forceinline__ void mma16(float* c, const uint32_t* a, const uint32_t* b) {
    asm volatile("mma.sync.aligned.m16n8k16.row.col.f32.bf16.bf16.f32 "
        "{%0,%1,%2,%3},{%4,%5,%6,%7},{%8,%9},{%0,%1,%2,%3};"
        : "+f"(c[0]), "+f"(c[1]), "+f"(c[2]), "+f"(c[3])
        : "r"(a[0]), "r"(a[1]), "r"(a[2]), "r"(a[3]), "r"(b[0]), "r"(b[1]));
}
__device__ __forceinline__ void ldsm_x4(uint32_t* r, uint32_t saddr) {
    asm volatile("ldmatrix.sync.aligned.m8n8.x4.shared.b16 {%0,%1,%2,%3}, [%4];"
        : "=r"(r[0]), "=r"(r[1]), "=r"(r[2]), "=r"(r[3]) : "r"(saddr));
}
__device__ __forceinline__ void split1(float x, bf16* hp, bf16* lp) {
    bf16 h = __float2bfloat16(x);
    *hp = h; *lp = __float2bfloat16(x - __bfloat162float(h));
}
__device__ __forceinline__ void split4(bf16* hp, bf16* lp, float4 v) {
    bf16 hx = __float2bfloat16(v.x), hy = __float2bfloat16(v.y);
    bf16 hz = __float2bfloat16(v.z), hw = __float2bfloat16(v.w);
    ((bf162*)hp)[0] = __halves2bfloat162(hx, hy);
    ((bf162*)hp)[1] = __halves2bfloat162(hz, hw);
    ((bf162*)lp)[0] = __halves2bfloat162(__float2bfloat16(v.x - __bfloat162float(hx)),
                                         __float2bfloat16(v.y - __bfloat162float(hy)));
    ((bf162*)lp)[1] = __halves2bfloat162(__float2bfloat16(v.z - __bfloat162float(hz)),
                                         __float2bfloat16(v.w - __bfloat162float(hw)));
}

// ---------------- split-bf16 tensor-core GEMM (ldmatrix operand path) ----------------
// C[M,Nper] = A[M,Kd] * B[Nper,Kd]^T + bias (A,B given as hi/lo bf16 planes).
// 3 MMAs per step: hi*hi + lo*hi + hi*lo. Dual weight sets via grid.x.
#define BK    32
#define BKP   40                 // padded smem row (bf16 elems); 80B stride -> ldmatrix conflict-free
#define STG_E (128*BKP)          // elems per plane per stage

extern __shared__ bf16 sm_dyn[];

__global__ __launch_bounds__(256, 2)
void gemm_bf16s(const bf16* __restrict__ Ah, const bf16* __restrict__ Al,
                const bf16* __restrict__ B0h, const bf16* __restrict__ B0l, const float* __restrict__ bias0,
                const bf16* __restrict__ B1h, const bf16* __restrict__ B1l, const float* __restrict__ bias1,
                int Nper, int Kd, int relu, int split,
                float* __restrict__ C0f, float* __restrict__ C1f,
                bf16* __restrict__ C0h, bf16* __restrict__ C0l,
                bf16* __restrict__ C1h, bf16* __restrict__ C1l)
{
    const int t  = threadIdx.x;
    const int m0 = blockIdx.y * 128;
    const int nblk = Nper / 128;
    const bf16 *Bh, *Bl; const float* bias; float* Cf; bf16 *Ch, *Cl; int n0;
    if ((int)blockIdx.x < nblk) { Bh=B0h; Bl=B0l; bias=bias0; Cf=C0f; Ch=C0h; Cl=C0l; n0=blockIdx.x*128; }
    else                        { Bh=B1h; Bl=B1l; bias=bias1; Cf=C1f; Ch=C1h; Cl=C1l; n0=(blockIdx.x-nblk)*128; }

    const int warp = t >> 5, lane = t & 31;
    const int wm = (warp & 3) * 32, wn = (warp >> 2) * 64;
    const int g = lane >> 2, tig = lane & 3;
    const int mtx = lane >> 3;            // ldmatrix matrix index 0..3

    // per-thread ldmatrix row addresses (element offsets within a plane-stage)
    const int arow = wm + ((mtx & 1) * 8) + (lane & 7);     // + mi*16
    const int acol = (mtx & 2) * 4;                         // + kk
    const int brow = wn + ((mtx >> 1) * 8) + (lane & 7);    // + nj*16
    const int bcol = (mtx & 1) * 8;                         // + kk
    const uint32_t aoff = (uint32_t)(arow * BKP + acol) * 2;
    const uint32_t boff = (uint32_t)(brow * BKP + bcol) * 2;

    const bf16* Abh = Ah + (size_t)m0 * Kd;
    const bf16* Abl = Al + (size_t)m0 * Kd;
    const bf16* Bbh = Bh + (size_t)n0 * Kd;
    const bf16* Bbl = Bl + (size_t)n0 * Kd;

    const uint32_t s0 = (uint32_t)__cvta_generic_to_shared(sm_dyn);
    const int nK = Kd / BK;

    auto issue = [&](int kt, int buf) {
        const int ko = kt * BK;
        const uint32_t stg = s0 + (uint32_t)buf * (STG_E * 2);
        #pragma unroll
        for (int c = t; c < 512; c += 256) {
            const int r = c >> 2, off = (c & 3) * 8;
            const uint32_t da = (uint32_t)((r * BKP + off) * 2);
            const size_t gof = (size_t)r * Kd + ko + off;
            cp_async16(stg + da,               Abh + gof);
            cp_async16(stg + 4*STG_E + da,     Abl + gof);
        }
        #pragma unroll
        for (int c = t; c < 512; c += 256) {
            const int r = c >> 2, off = (c & 3) * 8;
            const uint32_t da = (uint32_t)((r * BKP + off) * 2);
            const size_t gof = (size_t)r * Kd + ko + off;
            cp_async16(stg + 8*STG_E + da,     Bbh + gof);
            cp_async16(stg + 12*STG_E + da,    Bbl + gof);
        }
        asm volatile("cp.async.commit_group;" ::: "memory");
    };

    float acc[2][8][4];
    #pragma unroll
    for (int mi = 0; mi < 2; mi++)
        #pragma unroll
        for (int ni = 0; ni < 8; ni++)
            #pragma unroll
            for (int x = 0; x < 4; x++) acc[mi][ni][x] = 0.f;

    issue(0, 0);
    for (int kt = 0; kt < nK; kt++) {
        const int buf = kt & 1;
        if (kt + 1 < nK) { issue(kt + 1, buf ^ 1); asm volatile("cp.async.wait_group 1;" ::: "memory"); }
        else             { asm volatile("cp.async.wait_group 0;" ::: "memory"); }
        __syncthreads();
        // plane-stage byte bases
        const uint32_t bAh = s0 + (uint32_t)(0 + buf) * (STG_E * 2);
        const uint32_t bAl = s0 + (uint32_t)(2 + buf) * (STG_E * 2);
        const uint32_t bBh = s0 + (uint32_t)(4 + buf) * (STG_E * 2);
        const uint32_t bBl = s0 + (uint32_t)(6 + buf) * (STG_E * 2);
        #pragma unroll
        for (int kk = 0; kk < BK; kk += 16) {
            const uint32_t kb = (uint32_t)kk * 2;
            uint32_t ah[2][4], ax[2][4], bx[4][4];
            #pragma unroll
            for (int mi = 0; mi < 2; mi++)
                ldsm_x4(ah[mi], bAh + aoff + (uint32_t)(mi * 16 * BKP) * 2 + kb);
            #pragma unroll
            for (int nj = 0; nj < 4; nj++)
                ldsm_x4(bx[nj], bBh + boff + (uint32_t)(nj * 16 * BKP) * 2 + kb);
            #pragma unroll
            for (int mi = 0; mi < 2; mi++)
                #pragma unroll
                for (int ni = 0; ni < 8; ni++)
                    mma16(acc[mi][ni], ah[mi], &bx[ni >> 1][(ni & 1) * 2]);   // hi*hi
            #pragma unroll
            for (int mi = 0; mi < 2; mi++)
                ldsm_x4(ax[mi], bAl + aoff + (uint32_t)(mi * 16 * BKP) * 2 + kb);
            #pragma unroll
            for (int mi = 0; mi < 2; mi++)
                #pragma unroll
                for (int ni = 0; ni < 8; ni++)
                    mma16(acc[mi][ni], ax[mi], &bx[ni >> 1][(ni & 1) * 2]);   // lo*hi
            #pragma unroll
            for (int nj = 0; nj < 4; nj++)
                ldsm_x4(bx[nj], bBl + boff + (uint32_t)(nj * 16 * BKP) * 2 + kb);
            #pragma unroll
            for (int mi = 0; mi < 2; mi++)
                #pragma unroll
                for (int ni = 0; ni < 8; ni++)
                    mma16(acc[mi][ni], ah[mi], &bx[ni >> 1][(ni & 1) * 2]);   // hi*lo
        }
        __syncthreads();
    }

    #pragma unroll
    for (int mi = 0; mi < 2; mi++) {
        const int row0 = m0 + wm + mi*16 + g;
        #pragma unroll
        for (int ni = 0; ni < 8; ni++) {
            const int col = n0 + wn + ni*8 + 2*tig;
            const float b0v = bias[col], b1v = bias[col + 1];
            float v0 = acc[mi][ni][0] + b0v, v1 = acc[mi][ni][1] + b1v;
            float v2 = acc[mi][ni][2] + b0v, v3 = acc[mi][ni][3] + b1v;
            if (relu) { v0 = fmaxf(v0,0.f); v1 = fmaxf(v1,0.f); v2 = fmaxf(v2,0.f); v3 = fmaxf(v3,0.f); }
            if (!split) {
                *(float2*)(Cf + (size_t)row0 * Nper + col)     = make_float2(v0, v1);
                *(float2*)(Cf + (size_t)(row0+8) * Nper + col) = make_float2(v2, v3);
            } else {
                bf16 h0 = __float2bfloat16(v0), h1 = __float2bfloat16(v1);
                bf16 h2 = __float2bfloat16(v2), h3 = __float2bfloat16(v3);
                *(bf162*)(Ch + (size_t)row0 * Nper + col)     = __halves2bfloat162(h0, h1);
                *(bf162*)(Ch + (size_t)(row0+8) * Nper + col) = __halves2bfloat162(h2, h3);
                *(bf162*)(Cl + (size_t)row0 * Nper + col)     =
                    __halves2bfloat162(__float2bfloat16(v0 - __bfloat162float(h0)),
                                       __float2bfloat16(v1 - __bfloat162float(h1)));
                *(bf162*)(Cl + (size_t)(row0+8) * Nper + col) =
                    __halves2bfloat162(__float2bfloat16(v2 - __bfloat162float(h2)),
                                       __float2bfloat16(v3 - __bfloat162float(h3)));
            }
        }
    }
}

// ---------------- weight splitter: packed [rows, cols] hi/lo from fp32 [rows, ld] ----------------
__global__ void split_w(const float* __restrict__ src, bf16* __restrict__ hi, bf16* __restrict__ lo,
                        int total, int cols, int ld)
{
    const int i = blockIdx.x * 256 + threadIdx.x;
    if (i >= total) return;
    const int r = i / cols, c = i - r * cols;
    split1(src[(size_t)r * ld + c], hi + i, lo + i);
}

// ---------------- effective Q bias: qb[model][n] = bq[n] + sum_t Wq[n][128+t]*cos(tb[t]) ----------------
__global__ void make_qbias(const float* __restrict__ Wq, const float* __restrict__ bq,
                           const float* __restrict__ tb, float* __restrict__ qb)
{
    const int model = blockIdx.x, n = threadIdx.x;     // grid 2, block 256
    const float* w = Wq + (size_t)model * QDIM * QDIM + (size_t)n * QDIM + DD;
    float s = bq[model * QDIM + n];
    for (int t = 0; t < TT; t++) s += w[t] * cosf(tb[t]);
    qb[model * QDIM + n] = s;
}

// ---------------- gather emb0 for layer-1 src rows ----------------
__global__ void gather_src_l1(const float* __restrict__ nf, const float* __restrict__ mem,
                              const int* __restrict__ src_nodes, const int* __restrict__ n1flat,
                              bf16* __restrict__ dh, bf16* __restrict__ dl)
{
    const int m = blockIdx.x * 4 + (threadIdx.x >> 5);
    const int lane = threadIdx.x & 31;
    const int node = (m < BB) ? src_nodes[m] : n1flat[m - BB];
    const float4 a = ((const float4*)(nf  + (size_t)node * DD))[lane];
    const float4 b = ((const float4*)(mem + (size_t)node * DD))[lane];
    split4(dh + (size_t)m*DD + lane*4, dl + (size_t)m*DD + lane*4,
           make_float4(a.x+b.x, a.y+b.y, a.z+b.z, a.w+b.w));
}

// ---------------- keyv rows, layer-1 fused pass ----------------
__global__ void build_keyv_l1(const float* __restrict__ nf, const float* __restrict__ mem,
                              const float* __restrict__ ef,
                              const float* __restrict__ tw, const float* __restrict__ tb,
                              const int* __restrict__ n1, const int* __restrict__ e1,
                              const float* __restrict__ et1, const float* __restrict__ ts,
                              const int* __restrict__ n2, const int* __restrict__ e2,
                              const float* __restrict__ et2,
                              bf16* __restrict__ kvh, bf16* __restrict__ kvl)
{
    const int p = blockIdx.x * 4 + (threadIdx.x >> 5);
    const int lane = threadIdx.x & 31;
    const int m = p / KK;
    int node, eidx; float tm, et;
    if (m < BB) { node = n1[p]; eidx = e1[p]; tm = ts[m]; et = et1[p]; }
    else {
        const int pp = p - BB * KK;
        node = n2[pp]; eidx = e2[pp]; tm = ts[(m - BB) / KK]; et = et2[pp];
    }
    const float4 a = ((const float4*)(nf  + (size_t)node * DD))[lane];
    const float4 b = ((const float4*)(mem + (size_t)node * DD))[lane];
    const float4 e = ((const float4*)(ef  + (size_t)eidx * DD))[lane];
    const float4 w = ((const float4*)tw)[lane];
    const float4 bb = ((const float4*)tb)[lane];
    const float dt = tm - et;
    const size_t base = (size_t)p * KDIM + lane*4;
    split4(kvh + base,        kvl + base,        make_float4(a.x+b.x, a.y+b.y, a.z+b.z, a.w+b.w));
    split4(kvh + base + DD,   kvl + base + DD,   e);
    split4(kvh + base + 2*DD, kvl + base + 2*DD,
           make_float4(cosf(dt*w.x+bb.x), cosf(dt*w.y+bb.y), cosf(dt*w.z+bb.z), cosf(dt*w.w+bb.w)));
}

// ---------------- keyv rows, layer-2 pass (neighbor emb copied from out1 planes) ----------------
__global__ void build_keyv_l2(const bf16* __restrict__ nh, const bf16* __restrict__ nl,  // [MKC, DD]
                              const float* __restrict__ ef,
                              const float* __restrict__ tw, const float* __restrict__ tb,
                              const int* __restrict__ e1, const float* __restrict__ et1,
                              const float* __restrict__ ts,
                              bf16* __restrict__ kvh, bf16* __restrict__ kvl)
{
    const int p = blockIdx.x * 4 + (threadIdx.x >> 5);
    const int lane = threadIdx.x & 31;
    const int m = p / KK;
    const float4 e  = ((const float4*)(ef + (size_t)e1[p] * DD))[lane];
    const float4 w  = ((const float4*)tw)[lane];
    const float4 bb = ((const float4*)tb)[lane];
    const float dt = ts[m] - et1[p];
    const size_t base = (size_t)p * KDIM + lane*4;
    ((uint2*)(kvh + (size_t)p*KDIM))[lane] = ((const uint2*)(nh + (size_t)p*DD))[lane];
    ((uint2*)(kvl + (size_t)p*KDIM))[lane] = ((const uint2*)(nl + (size_t)p*DD))[lane];
    split4(kvh + base + DD,   kvl + base + DD,   e);
    split4(kvh + base + 2*DD, kvl + base + 2*DD,
           make_float4(cosf(dt*w.x+bb.x), cosf(dt*w.y+bb.y), cosf(dt*w.z+bb.z), cosf(dt*w.w+bb.w)));
}

// ---------------- scores + masked softmax + context ----------------
__global__ void attn_combine(const float* __restrict__ q, const float* __restrict__ k,
                             const float* __restrict__ v,
                             const int* __restrict__ neighA, const int* __restrict__ neighB,
                             int boundary,
                             bf16* __restrict__ ch, bf16* __restrict__ cl,
                             unsigned char* __restrict__ inv)
{
    const int m = blockIdx.x, t = threadIdx.x;             // 256 threads
    __shared__ int   smask[KK];
    __shared__ float ssc[2][KK];
    __shared__ float sw[2][KK];

    if (t < KK) {
        const int* nb = (m < boundary) ? (neighA + (size_t)m * KK)
                                       : (neighB + (size_t)(m - boundary) * KK);
        smask[t] = (nb[t] == 0);
    }
    const int warp = t >> 5, lane = t & 31;
    for (int task = warp; task < 2 * KK; task += 8) {
        const int j = task >> 1, h = task & 1;
        const float* qr = q + (size_t)m * QDIM + h * 128;
        const float* kr = k + ((size_t)m * KK + j) * QDIM + h * 128;
        float s = 0.f;
        #pragma unroll
        for (int i = 0; i < 4; i++) { const int c = lane + 32 * i; s += qr[c] * kr[c]; }
        #pragma unroll
        for (int o = 16; o; o >>= 1) s += __shfl_xor_sync(0xffffffffu, s, o);
        if (lane == 0) ssc[h][j] = s * 0.08838834764831845f;   // 1/sqrt(128)
    }
    __syncthreads();

    if (t < 2) {
        const int h = t;
        int all1 = 1;
        #pragma unroll
        for (int j = 0; j < KK; j++) all1 &= smask[j];
        float sv[KK]; float mx = -3.0e38f;
        #pragma unroll
        for (int j = 0; j < KK; j++) {
            const int mk = smask[j] && !(all1 && j == 0);
            sv[j] = mk ? -1e9f : ssc[h][j];
            mx = fmaxf(mx, sv[j]);
        }
        float den = 0.f;
        #pragma unroll
        for (int j = 0; j < KK; j++) { const float e = expf(sv[j] - mx); sw[h][j] = e; den += e; }
        const float r = 1.f / den;
        #pragma unroll
        for (int j = 0; j < KK; j++) sw[h][j] *= r;
        if (t == 0) inv[m] = (unsigned char)all1;
    }
    __syncthreads();

    const int h = t >> 7;
    float acc = 0.f;
    #pragma unroll
    for (int j = 0; j < KK; j++)
        acc += sw[h][j] * v[((size_t)m * KK + j) * QDIM + t];
    split1(acc, ch + (size_t)m * QDIM + t, cl + (size_t)m * QDIM + t);
}

// ---------------- g = [invalid ? 0 : o  ||  src_feat] ----------------
__global__ void build_g(const float* __restrict__ o,
                        const bf16* __restrict__ sh, const bf16* __restrict__ sl,
                        const unsigned char* __restrict__ inv,
                        bf16* __restrict__ gh, bf16* __restrict__ gl)
{
    const int m = blockIdx.x, t = threadIdx.x;             // 384 threads
    const size_t idx = (size_t)m * KDIM + t;
    if (t < QDIM) {
        const float val = inv[m] ? 0.f : o[(size_t)m * QDIM + t];
        split1(val, gh + idx, gl + idx);
    } else {
        gh[idx] = sh[(size_t)m * DD + (t - QDIM)];
        gl[idx] = sl[(size_t)m * DD + (t - QDIM)];
    }
}

// ---------------- host launcher ----------------
#define GEMM_SMEM (8 * STG_E * 2)    // 81920 bytes

extern "C" void kernel_launch(void* const* d_in, const int* in_sizes, int n_in,
                              void* d_out, int out_size)
{
    const float* node_feat   = (const float*)d_in[0];
    const float* memory      = (const float*)d_in[1];
    const float* edge_feat   = (const float*)d_in[2];
    const float* time_w      = (const float*)d_in[3];
    const float* time_b      = (const float*)d_in[4];
    const float* Wq          = (const float*)d_in[5];
    const float* bq          = (const float*)d_in[6];
    const float* Wk          = (const float*)d_in[7];
    const float* bk          = (const float*)d_in[8];
    const float* Wv          = (const float*)d_in[9];
    const float* bv          = (const float*)d_in[10];
    const float* Wo          = (const float*)d_in[11];
    const float* bo          = (const float*)d_in[12];
    const float* W1          = (const float*)d_in[13];
    const float* b1          = (const float*)d_in[14];
    const float* W2          = (const float*)d_in[15];
    const float* b2          = (const float*)d_in[16];
    const float* timestamps  = (const float*)d_in[17];
    const int*   src_nodes   = (const int*)d_in[18];
    const int*   neighbors1  = (const int*)d_in[19];
    const int*   edge_idx1   = (const int*)d_in[20];
    const float* edge_times1 = (const float*)d_in[21];
    const int*   neighbors2  = (const int*)d_in[22];
    const int*   edge_idx2   = (const int*)d_in[23];
    const float* edge_times2 = (const float*)d_in[24];
    float* out = (float*)d_out;

    bf16 *srch, *srcl, *kvh, *kvl, *ctxh, *ctxl, *ggh, *ggl, *hh, *hl, *o1h, *o1l;
    bf16 *wqh, *wql, *wkh, *wkl, *wvh, *wvl, *woh, *wol, *w1h, *w1l, *w2h, *w2l;
    float *pq, *pk, *pv, *po, *pqb;
    unsigned char* pinv;
    cudaGetSymbolAddress((void**)&srch, g_src_h); cudaGetSymbolAddress((void**)&srcl, g_src_l);
    cudaGetSymbolAddress((void**)&kvh,  g_kv_h);  cudaGetSymbolAddress((void**)&kvl,  g_kv_l);
    cudaGetSymbolAddress((void**)&ctxh, g_ctx_h); cudaGetSymbolAddress((void**)&ctxl, g_ctx_l);
    cudaGetSymbolAddress((void**)&ggh,  g_gg_h);  cudaGetSymbolAddress((void**)&ggl,  g_gg_l);
    cudaGetSymbolAddress((void**)&hh,   g_h_h);   cudaGetSymbolAddress((void**)&hl,   g_h_l);
    cudaGetSymbolAddress((void**)&o1h,  g_o1_h);  cudaGetSymbolAddress((void**)&o1l,  g_o1_l);
    cudaGetSymbolAddress((void**)&wqh,  w_q_h);   cudaGetSymbolAddress((void**)&wql,  w_q_l);
    cudaGetSymbolAddress((void**)&wkh,  w_k_h);   cudaGetSymbolAddress((void**)&wkl,  w_k_l);
    cudaGetSymbolAddress((void**)&wvh,  w_v_h);   cudaGetSymbolAddress((void**)&wvl,  w_v_l);
    cudaGetSymbolAddress((void**)&woh,  w_o_h);   cudaGetSymbolAddress((void**)&wol,  w_o_l);
    cudaGetSymbolAddress((void**)&w1h,  w_1_h);   cudaGetSymbolAddress((void**)&w1l,  w_1_l);
    cudaGetSymbolAddress((void**)&w2h,  w_2_h);   cudaGetSymbolAddress((void**)&w2l,  w_2_l);
    cudaGetSymbolAddress((void**)&pq,   g_q);     cudaGetSymbolAddress((void**)&pk,   g_k);
    cudaGetSymbolAddress((void**)&pv,   g_v);     cudaGetSymbolAddress((void**)&po,   g_o);
    cudaGetSymbolAddress((void**)&pqb,  g_qb);    cudaGetSymbolAddress((void**)&pinv, g_inv);

    cudaFuncSetAttribute(gemm_bf16s, cudaFuncAttributeMaxDynamicSharedMemorySize, GEMM_SMEM);

    // ---- weight prep (tiny) ----
    make_qbias<<<2, QDIM>>>(Wq, bq, time_b, pqb);
    split_w<<<(2*QDIM*DD   + 255)/256, 256>>>(Wq, wqh, wql, 2*QDIM*DD,   DD,   QDIM);
    split_w<<<(2*QDIM*KDIM + 255)/256, 256>>>(Wk, wkh, wkl, 2*QDIM*KDIM, KDIM, KDIM);
    split_w<<<(2*QDIM*KDIM + 255)/256, 256>>>(Wv, wvh, wvl, 2*QDIM*KDIM, KDIM, KDIM);
    split_w<<<(2*QDIM*QDIM + 255)/256, 256>>>(Wo, woh, wol, 2*QDIM*QDIM, QDIM, QDIM);
    split_w<<<(2*DD*KDIM   + 255)/256, 256>>>(W1, w1h, w1l, 2*DD*KDIM,   KDIM, KDIM);
    split_w<<<(2*DD*DD     + 255)/256, 256>>>(W2, w2h, w2l, 2*DD*DD,     DD,   DD);

    // model-1 plane offsets
    const int OQ = QDIM*DD, OK = QDIM*KDIM, OO = QDIM*QDIM, O1 = DD*KDIM, O2 = DD*DD;
    const float* bk1 = bk + QDIM; const float* bv1 = bv + QDIM; const float* bo1 = bo + QDIM;
    const float* b11 = b1 + DD;   const float* b21 = b2 + DD;

    // ================= fused layer-1 pass (model 0), M = MU =================
    gather_src_l1<<<MU/4, 128>>>(node_feat, memory, src_nodes, neighbors1, srch, srcl);
    gemm_bf16s<<<dim3(2, MU/128), 256, GEMM_SMEM>>>(srch, srcl, wqh, wql, pqb, wqh, wql, pqb,
        QDIM, DD, 0, 0, pq, pq, 0, 0, 0, 0);
    build_keyv_l1<<<MKU/4, 128>>>(node_feat, memory, edge_feat, time_w, time_b,
                                  neighbors1, edge_idx1, edge_times1, timestamps,
                                  neighbors2, edge_idx2, edge_times2, kvh, kvl);
    gemm_bf16s<<<dim3(4, MKU/128), 256, GEMM_SMEM>>>(kvh, kvl, wkh, wkl, bk, wvh, wvl, bv,
        QDIM, KDIM, 0, 0, pk, pv, 0, 0, 0, 0);
    attn_combine<<<MU, 256>>>(pq, pk, pv, neighbors1, neighbors2, BB, ctxh, ctxl, pinv);
    gemm_bf16s<<<dim3(2, MU/128), 256, GEMM_SMEM>>>(ctxh, ctxl, woh, wol, bo, woh, wol, bo,
        QDIM, QDIM, 0, 0, po, po, 0, 0, 0, 0);
    build_g<<<MU, KDIM>>>(po, srch, srcl, pinv, ggh, ggl);
    gemm_bf16s<<<dim3(1, MU/128), 256, GEMM_SMEM>>>(ggh, ggl, w1h, w1l, b1, w1h, w1l, b1,
        DD, KDIM, 1, 1, 0, 0, hh, hl, hh, hl);
    gemm_bf16s<<<dim3(1, MU/128), 256, GEMM_SMEM>>>(hh, hl, w2h, w2l, b2, w2h, w2l, b2,
        DD, DD, 0, 1, 0, 0, o1h, o1l, o1h, o1l);

    // ================= layer-2 pass (model 1), M = BB =================
    gemm_bf16s<<<dim3(2, BB/128), 256, GEMM_SMEM>>>(o1h, o1l, wqh+OQ, wql+OQ, pqb+QDIM, wqh+OQ, wql+OQ, pqb+QDIM,
        QDIM, DD, 0, 0, pq, pq, 0, 0, 0, 0);
    build_keyv_l2<<<MKC/4, 128>>>(o1h + (size_t)BB*DD, o1l + (size_t)BB*DD, edge_feat, time_w, time_b,
                                  edge_idx1, edge_times1, timestamps, kvh, kvl);
    gemm_bf16s<<<dim3(4, MKC/128), 256, GEMM_SMEM>>>(kvh, kvl, wkh+OK, wkl+OK, bk1, wvh+OK, wvl+OK, bv1,
        QDIM, KDIM, 0, 0, pk, pv, 0, 0, 0, 0);
    attn_combine<<<BB, 256>>>(pq, pk, pv, neighbors1, neighbors1, BB, ctxh, ctxl, pinv);
    gemm_bf16s<<<dim3(2, BB/128), 256, GEMM_SMEM>>>(ctxh, ctxl, woh+OO, wol+OO, bo1, woh+OO, wol+OO, bo1,
        QDIM, QDIM, 0, 0, po, po, 0, 0, 0, 0);
    build_g<<<BB, KDIM>>>(po, o1h, o1l, pinv, ggh, ggl);
    gemm_bf16s<<<dim3(1, BB/128), 256, GEMM_SMEM>>>(ggh, ggl, w1h+O1, w1l+O1, b11, w1h+O1, w1l+O1, b11,
        DD, KDIM, 1, 1, 0, 0, hh, hl, hh, hl);
    gemm_bf16s<<<dim3(1, BB/128), 256, GEMM_SMEM>>>(hh, hl, w2h+O2, w2l+O2, b21, w2h+O2, w2l+O2, b21,
        DD, DD, 0, 0, out, out, 0, 0, 0, 0);
}